// round 1
// baseline (speedup 1.0000x reference)
#include <cuda_runtime.h>

// Causal GQA attention, fp32 flash-attention (SIMT baseline).
// B=2, S=2048, H=32, HK=8 (rep 4), D=128.
// q: [B*S, H*D], k/v: [B*S, HK*D], out: [B*S, H*D]

#define SEQ 2048
#define NH 32
#define NHK 8
#define HD 128
#define BQ 64      // query rows per CTA
#define BK 64      // keys per tile
#define NTHREADS 256
#define RPW 8      // rows per warp (BQ / 8 warps)

__global__ __launch_bounds__(NTHREADS, 2)
void fattn_kernel(const float* __restrict__ qg,
                  const float* __restrict__ kg,
                  const float* __restrict__ vg,
                  float* __restrict__ outg) {
    extern __shared__ float4 smem[];
    float4* sQ = smem;          // [64 rows][32 quads]  (pre-scaled)
    float4* sK = smem + 2048;   // [32 quads][64 keys]  quad-transposed
    float4* sV = smem + 4096;   // [64 keys][32 quads]

    const int tid  = threadIdx.x;
    const int lane = tid & 31;
    const int wid  = tid >> 5;
    const int qt = blockIdx.x;        // query tile: 0..31
    const int h  = blockIdx.y;        // head
    const int b  = blockIdx.z;        // batch
    const int hk = h >> 2;            // GQA: 4 q-heads per kv-head
    const int q0 = qt * BQ;

    // SCALE * log2(e): softmax computed in exp2 domain.
    const float qscale = 0.08838834764831845f * 1.4426950408889634f;

    // ---- load Q tile (coalesced, conflict-free) ----
    {
        const int qbase = (b * SEQ + q0) * (NH * HD) + h * HD;
        #pragma unroll
        for (int i = 0; i < 8; i++) {
            int idx = tid + i * NTHREADS;   // idx = r*32 + c
            int r = idx >> 5, c = idx & 31;
            float4 val = *(const float4*)(qg + qbase + r * (NH * HD) + c * 4);
            val.x *= qscale; val.y *= qscale; val.z *= qscale; val.w *= qscale;
            sQ[idx] = val;
        }
    }

    const int wrow = wid * RPW;   // first row (within tile) owned by this warp
    float m_run[RPW], l_run[RPW];
    float4 o[RPW];
    #pragma unroll
    for (int rr = 0; rr < RPW; rr++) {
        m_run[rr] = -1e30f; l_run[rr] = 0.f;
        o[rr] = make_float4(0.f, 0.f, 0.f, 0.f);
    }

    for (int kt = 0; kt <= qt; kt++) {
        const int k0 = kt * BK;
        const int kbase = (b * SEQ + k0) * (NHK * HD) + hk * HD;

        // K tile: store quad-transposed sK[c][j] = K[j][4c..4c+3].
        // j-fast mapping -> conflict-free STS128 (global side is strided; L2 absorbs it).
        #pragma unroll
        for (int i = 0; i < 8; i++) {
            int idx = tid + i * NTHREADS;   // idx = c*64 + j
            int c = idx >> 6, j = idx & 63;
            sK[c * 64 + j] = *(const float4*)(kg + kbase + j * (NHK * HD) + c * 4);
        }
        // V tile: row-major, fully coalesced + conflict-free.
        #pragma unroll
        for (int i = 0; i < 8; i++) {
            int idx = tid + i * NTHREADS;   // idx = j*32 + c
            int j = idx >> 5, c = idx & 31;
            sV[idx] = *(const float4*)(vg + kbase + j * (NHK * HD) + c * 4);
        }
        __syncthreads();

        // ---- QK^T: each lane owns keys {lane, lane+32}, 8 rows ----
        float s0[RPW], s1[RPW];
        #pragma unroll
        for (int rr = 0; rr < RPW; rr++) { s0[rr] = 0.f; s1[rr] = 0.f; }

        #pragma unroll 4
        for (int dq = 0; dq < 32; dq++) {
            float4 k0v = sK[dq * 64 + lane];        // LDS128, conflict-free
            float4 k1v = sK[dq * 64 + lane + 32];
            #pragma unroll
            for (int rr = 0; rr < RPW; rr++) {
                float4 qv = sQ[(wrow + rr) * 32 + dq];  // broadcast
                s0[rr] += qv.x * k0v.x + qv.y * k0v.y + qv.z * k0v.z + qv.w * k0v.w;
                s1[rr] += qv.x * k1v.x + qv.y * k1v.y + qv.z * k1v.z + qv.w * k1v.w;
            }
        }

        // ---- causal mask (diagonal tile only) + online softmax ----
        const bool diag = (kt == qt);
        #pragma unroll
        for (int rr = 0; rr < RPW; rr++) {
            const int rloc = wrow + rr;
            if (diag) {
                if (lane > rloc)       s0[rr] = -1e30f;
                if (lane + 32 > rloc)  s1[rr] = -1e30f;
            }
            float mx = fmaxf(s0[rr], s1[rr]);
            #pragma unroll
            for (int off = 16; off; off >>= 1)
                mx = fmaxf(mx, __shfl_xor_sync(0xffffffffu, mx, off));
            float m_new = fmaxf(m_run[rr], mx);
            float p0 = exp2f(s0[rr] - m_new);
            float p1 = exp2f(s1[rr] - m_new);
            s0[rr] = p0; s1[rr] = p1;                 // reuse as probabilities
            float rs = p0 + p1;
            #pragma unroll
            for (int off = 16; off; off >>= 1)
                rs += __shfl_xor_sync(0xffffffffu, rs, off);
            float corr = exp2f(m_run[rr] - m_new);
            l_run[rr] = l_run[rr] * corr + rs;
            m_run[rr] = m_new;
            o[rr].x *= corr; o[rr].y *= corr; o[rr].z *= corr; o[rr].w *= corr;
        }

        // ---- P·V: broadcast probabilities via shfl; each lane owns dims lane*4..+3 ----
        #pragma unroll 2
        for (int j = 0; j < 32; j++) {
            float4 v0 = sV[j * 32 + lane];
            float4 v1 = sV[(j + 32) * 32 + lane];
            #pragma unroll
            for (int rr = 0; rr < RPW; rr++) {
                float pj = __shfl_sync(0xffffffffu, s0[rr], j);
                o[rr].x += pj * v0.x; o[rr].y += pj * v0.y;
                o[rr].z += pj * v0.z; o[rr].w += pj * v0.w;
                float pj2 = __shfl_sync(0xffffffffu, s1[rr], j);
                o[rr].x += pj2 * v1.x; o[rr].y += pj2 * v1.y;
                o[rr].z += pj2 * v1.z; o[rr].w += pj2 * v1.w;
            }
        }
        __syncthreads();
    }

    // ---- epilogue: normalize & write ----
    #pragma unroll
    for (int rr = 0; rr < RPW; rr++) {
        float inv = 1.0f / l_run[rr];
        float4 r = o[rr];
        r.x *= inv; r.y *= inv; r.z *= inv; r.w *= inv;
        int row = b * SEQ + q0 + wrow + rr;
        *(float4*)(outg + (size_t)row * (NH * HD) + h * HD + lane * 4) = r;
    }
}

extern "C" void kernel_launch(void* const* d_in, const int* in_sizes, int n_in,
                              void* d_out, int out_size) {
    const float* q = (const float*)d_in[0];
    const float* k = (const float*)d_in[1];
    const float* v = (const float*)d_in[2];
    float* out = (float*)d_out;

    const int smem_bytes = 3 * BQ * HD * (int)sizeof(float);  // 98304
    cudaFuncSetAttribute(fattn_kernel,
                         cudaFuncAttributeMaxDynamicSharedMemorySize, smem_bytes);

    dim3 grid(SEQ / BQ, NH, 2);   // (32, 32, 2)
    fattn_kernel<<<grid, NTHREADS, smem_bytes>>>(q, k, v, out);
}

// round 4
// speedup vs baseline: 3.1809x; 3.1809x over previous
#include <cuda_runtime.h>
#include <cstdint>

// Causal GQA attention via warp-level mma.sync tf32 (plain sm_103 target).
// B=2, S=2048, H=32, HK=8 (rep 4), D=128. fp32 in/out.
// Max-free softmax: p = exp2(s); O, l accumulate across key tiles; normalize once.
// Precision: rna-rounded tf32 operands everywhere + hi/lo split of P for PV.

#define SEQ 2048
#define NH 32
#define NHK 8
#define HD 128
#define QSTR (NH*HD)    // 4096
#define KSTR (NHK*HD)   // 1024
#define BQ 64
#define BK 64
#define NTHREADS 128

// smem layout (bytes). P_hi/P_lo alias sK (K dead after QK mma).
#define SQ_OFF 0                      // 64 rows x 512B, swizzled 16B chunks
#define SK_OFF 32768                  // 64 rows x 512B, swizzled
#define SV_OFF 65536                  // 64 rows x 544B (128f + 8f pad), linear
#define SPH_OFF SK_OFF                // 64 rows x 256B, swizzled (P hi)
#define SPL_OFF (SK_OFF + 16384)      // 64 rows x 256B, swizzled (P lo)
#define SMEM_BYTES (SV_OFF + 64*544)  // 100352

static __device__ __forceinline__ uint32_t smem_u32(const void* p){
    uint32_t a;
    asm("{ .reg .u64 t; cvta.to.shared.u64 t, %1; cvt.u32.u64 %0, t; }" : "=r"(a) : "l"(p));
    return a;
}

// round-to-nearest f32 -> tf32 (kept in f32 container)
static __device__ __forceinline__ float tf32r(float x){
    uint32_t u;
    asm("cvt.rna.tf32.f32 %0, %1;" : "=r"(u) : "f"(x));
    return __uint_as_float(u);
}
static __device__ __forceinline__ float4 tf32r4(float4 v){
    v.x = tf32r(v.x); v.y = tf32r(v.y); v.z = tf32r(v.z); v.w = tf32r(v.w);
    return v;
}

static __device__ __forceinline__ void ldm4(uint32_t* r, uint32_t addr){
    asm volatile("ldmatrix.sync.aligned.m8n8.x4.shared.b16 {%0,%1,%2,%3}, [%4];"
                 : "=r"(r[0]), "=r"(r[1]), "=r"(r[2]), "=r"(r[3]) : "r"(addr));
}

static __device__ __forceinline__ void mma8(float* d, const uint32_t* a,
                                            uint32_t b0, uint32_t b1){
    asm volatile(
        "mma.sync.aligned.m16n8k8.row.col.f32.tf32.tf32.f32 "
        "{%0,%1,%2,%3}, {%4,%5,%6,%7}, {%8,%9}, {%0,%1,%2,%3};"
        : "+f"(d[0]), "+f"(d[1]), "+f"(d[2]), "+f"(d[3])
        : "r"(a[0]), "r"(a[1]), "r"(a[2]), "r"(a[3]), "r"(b0), "r"(b1));
}

__global__ __launch_bounds__(NTHREADS, 2)
void fattn_mma(const float* __restrict__ qg, const float* __restrict__ kg,
               const float* __restrict__ vg, float* __restrict__ outg)
{
    extern __shared__ char smem[];
    const uint32_t smb = smem_u32(smem);
    const uint32_t sQb  = smb + SQ_OFF;
    const uint32_t sKb  = smb + SK_OFF;
    const uint32_t sPhb = smb + SPH_OFF;
    const uint32_t sPlb = smb + SPL_OFF;

    const int tid  = threadIdx.x;
    const int lane = tid & 31;
    const int w    = tid >> 5;          // warp 0..3, owns q-rows 16w..16w+15
    const int g    = lane >> 2;         // group id
    const int tig  = lane & 3;          // thread-in-group
    const int mi   = lane >> 3;         // ldmatrix matrix id 0..3
    const int r8   = lane & 7;          // ldmatrix row-in-matrix
    const int hiA  = mi >> 1;           // A-frag chunk offset (0/1)
    const int hiB  = lane >> 3;         // B-frag chunk offset (0..3)
    const int rowA = w*16 + (mi & 1)*8 + r8;

    const int qt = (int)(gridDim.x - 1 - blockIdx.x);   // heavy tiles first
    const int h  = blockIdx.y;
    const int b  = blockIdx.z;
    const int hk = h >> 2;
    const int q0 = qt * BQ;

    // ---- stage Q (scaled by SCALE*log2e, rna-rounded to tf32) ----
    {
        const float qsc = 0.08838834764831845f * 1.4426950408889634f;
        const float* qs = qg + (size_t)(b*SEQ + q0)*QSTR + h*HD;
        #pragma unroll
        for (int i = 0; i < 16; i++) {
            int idx = i*NTHREADS + tid;
            int r = idx >> 5, c = idx & 31;
            float4 v = *(const float4*)(qs + (size_t)r*QSTR + c*4);
            v.x *= qsc; v.y *= qsc; v.z *= qsc; v.w *= qsc;
            *(float4*)(smem + SQ_OFF + r*512 + ((c ^ (r & 7)) << 4)) = tf32r4(v);
        }
    }

    float o[16][4];
    #pragma unroll
    for (int nt = 0; nt < 16; nt++)
        o[nt][0] = o[nt][1] = o[nt][2] = o[nt][3] = 0.f;
    float l0 = 0.f, l8 = 0.f;

    const uint32_t aQbase  = sQb  + rowA*512;
    const uint32_t aPhbase = sPhb + rowA*256;
    const uint32_t aPlbase = sPlb + rowA*256;
    const uint32_t bKbase  = sKb  + r8*512;

    for (int kt = 0; kt <= qt; kt++) {
        __syncthreads();   // all warps done reading prev sK/sV/sP
        const int k0 = kt * BK;
        const float* ksrc = kg + (size_t)(b*SEQ + k0)*KSTR + hk*HD;
        const float* vsrc = vg + (size_t)(b*SEQ + k0)*KSTR + hk*HD;
        #pragma unroll
        for (int i = 0; i < 16; i++) {
            int idx = i*NTHREADS + tid;
            int r = idx >> 5, c = idx & 31;
            *(float4*)(smem + SK_OFF + r*512 + ((c ^ (r & 7)) << 4)) =
                tf32r4(*(const float4*)(ksrc + (size_t)r*KSTR + c*4));
            *(float4*)(smem + SV_OFF + r*544 + c*16) =
                tf32r4(*(const float4*)(vsrc + (size_t)r*KSTR + c*4));
        }
        __syncthreads();   // tiles ready

        // ---- QK^T: S(16x64 per warp) += Q_w(16x128) @ K^T ----
        float s[8][4];
        #pragma unroll
        for (int nt = 0; nt < 8; nt++)
            s[nt][0] = s[nt][1] = s[nt][2] = s[nt][3] = 0.f;

        #pragma unroll
        for (int kp = 0; kp < 8; kp++) {          // d += 16 per iter
            uint32_t A0[4], A1[4];
            ldm4(A0, aQbase + (((4*kp     + hiA) ^ r8) << 4));
            ldm4(A1, aQbase + (((4*kp + 2 + hiA) ^ r8) << 4));
            #pragma unroll
            for (int nt = 0; nt < 8; nt++) {
                uint32_t B[4];
                ldm4(B, bKbase + nt*4096 + (((4*kp + hiB) ^ r8) << 4));
                mma8(s[nt], A0, B[0], B[1]);
                mma8(s[nt], A1, B[2], B[3]);
            }
        }
        __syncthreads();   // all warps done reading sK (P buffers alias it)

        // ---- softmax (max-free) + hi/lo split of P -> smem ----
        const bool diag = (kt == qt);
        const int rl0 = w*16 + g;
        #pragma unroll
        for (int nt = 0; nt < 8; nt++) {
            float p0 = exp2f(s[nt][0]);
            float p1 = exp2f(s[nt][1]);
            float p2 = exp2f(s[nt][2]);
            float p3 = exp2f(s[nt][3]);
            if (diag) {
                int c = nt*8 + 2*tig;
                if (c     > rl0)     p0 = 0.f;
                if (c + 1 > rl0)     p1 = 0.f;
                if (c     > rl0 + 8) p2 = 0.f;
                if (c + 1 > rl0 + 8) p3 = 0.f;
            }
            l0 += p0 + p1;
            l8 += p2 + p3;
            float h0 = tf32r(p0), h1 = tf32r(p1), h2 = tf32r(p2), h3 = tf32r(p3);
            int swz = (((2*nt + (tig >> 1)) ^ g) << 4) + (tig & 1)*8;
            *(float2*)(smem + SPH_OFF + rl0*256     + swz) = make_float2(h0, h1);
            *(float2*)(smem + SPH_OFF + (rl0+8)*256 + swz) = make_float2(h2, h3);
            *(float2*)(smem + SPL_OFF + rl0*256     + swz) =
                make_float2(tf32r(p0 - h0), tf32r(p1 - h1));
            *(float2*)(smem + SPL_OFF + (rl0+8)*256 + swz) =
                make_float2(tf32r(p2 - h2), tf32r(p3 - h3));
        }
        __syncwarp();      // own P rows visible to own ldmatrix

        // ---- P·V: O += (P_hi + P_lo) @ V ----
        #pragma unroll
        for (int kp = 0; kp < 4; kp++) {          // keys += 16 per iter
            uint32_t A0h[4], A1h[4], A0l[4], A1l[4];
            ldm4(A0h, aPhbase + (((4*kp     + hiA) ^ r8) << 4));
            ldm4(A1h, aPhbase + (((4*kp + 2 + hiA) ^ r8) << 4));
            ldm4(A0l, aPlbase + (((4*kp     + hiA) ^ r8) << 4));
            ldm4(A1l, aPlbase + (((4*kp + 2 + hiA) ^ r8) << 4));
            #pragma unroll
            for (int nt = 0; nt < 16; nt++) {
                const char* vb = smem + SV_OFF + (8*nt + g)*4;
                uint32_t b00 = *(const uint32_t*)(vb + (16*kp + tig     )*544);
                uint32_t b01 = *(const uint32_t*)(vb + (16*kp + tig + 4 )*544);
                uint32_t b10 = *(const uint32_t*)(vb + (16*kp + tig + 8 )*544);
                uint32_t b11 = *(const uint32_t*)(vb + (16*kp + tig + 12)*544);
                mma8(o[nt], A0h, b00, b01);
                mma8(o[nt], A1h, b10, b11);
                mma8(o[nt], A0l, b00, b01);
                mma8(o[nt], A1l, b10, b11);
            }
        }
    }

    // ---- epilogue: quad-reduce l, normalize, store ----
    l0 += __shfl_xor_sync(0xffffffffu, l0, 1);
    l0 += __shfl_xor_sync(0xffffffffu, l0, 2);
    l8 += __shfl_xor_sync(0xffffffffu, l8, 1);
    l8 += __shfl_xor_sync(0xffffffffu, l8, 2);
    const float i0 = 1.0f / l0;
    const float i8 = 1.0f / l8;

    float* og = outg + (size_t)(b*SEQ + q0 + w*16 + g)*QSTR + h*HD + 2*tig;
    #pragma unroll
    for (int nt = 0; nt < 16; nt++) {
        *(float2*)(og + nt*8)          = make_float2(o[nt][0]*i0, o[nt][1]*i0);
        *(float2*)(og + 8*QSTR + nt*8) = make_float2(o[nt][2]*i8, o[nt][3]*i8);
    }
}

extern "C" void kernel_launch(void* const* d_in, const int* in_sizes, int n_in,
                              void* d_out, int out_size) {
    const float* q = (const float*)d_in[0];
    const float* k = (const float*)d_in[1];
    const float* v = (const float*)d_in[2];
    float* out = (float*)d_out;

    cudaFuncSetAttribute(fattn_mma, cudaFuncAttributeMaxDynamicSharedMemorySize,
                         SMEM_BYTES);
    dim3 grid(SEQ / BQ, NH, 2);   // (32, 32, 2)
    fattn_mma<<<grid, NTHREADS, SMEM_BYTES>>>(q, k, v, out);
}

// round 5
// speedup vs baseline: 4.9512x; 1.5565x over previous
#include <cuda_runtime.h>
#include <cstdint>

// Causal GQA attention via warp-level mma.sync tf32 (plain sm_103 target).
// B=2, S=2048, H=32, HK=8 (rep 4), D=128. fp32 in/out.
// Max-free softmax; Q held as register A-fragments; K/V staged by cp.async
// pipeline; P (rna tf32) round-trips through dedicated smem region.

#define SEQ 2048
#define NH 32
#define NHK 8
#define HD 128
#define QSTR (NH*HD)    // 4096
#define KSTR (NHK*HD)   // 1024
#define BQ 64
#define BK 64
#define NTHREADS 128

// smem layout (bytes)
#define SK_OFF 0                      // 64 rows x 512B, swizzled 16B chunks
#define SP_OFF 32768                  // 64 rows x 256B, swizzled
#define SV_OFF 49152                  // 64 rows x 544B (128f + pad), linear
#define SMEM_BYTES (SV_OFF + 64*544)  // 83968

static __device__ __forceinline__ uint32_t smem_u32(const void* p){
    uint32_t a;
    asm("{ .reg .u64 t; cvta.to.shared.u64 t, %1; cvt.u32.u64 %0, t; }" : "=r"(a) : "l"(p));
    return a;
}
static __device__ __forceinline__ float tf32r(float x){
    uint32_t u;
    asm("cvt.rna.tf32.f32 %0, %1;" : "=r"(u) : "f"(x));
    return __uint_as_float(u);
}
static __device__ __forceinline__ void ldm4(uint32_t* r, uint32_t addr){
    asm volatile("ldmatrix.sync.aligned.m8n8.x4.shared.b16 {%0,%1,%2,%3}, [%4];"
                 : "=r"(r[0]), "=r"(r[1]), "=r"(r[2]), "=r"(r[3]) : "r"(addr));
}
static __device__ __forceinline__ void mma8(float* d, const uint32_t* a,
                                            uint32_t b0, uint32_t b1){
    asm volatile(
        "mma.sync.aligned.m16n8k8.row.col.f32.tf32.tf32.f32 "
        "{%0,%1,%2,%3}, {%4,%5,%6,%7}, {%8,%9}, {%0,%1,%2,%3};"
        : "+f"(d[0]), "+f"(d[1]), "+f"(d[2]), "+f"(d[3])
        : "r"(a[0]), "r"(a[1]), "r"(a[2]), "r"(a[3]), "r"(b0), "r"(b1));
}
static __device__ __forceinline__ void cpa16(uint32_t dst, const void* src){
    asm volatile("cp.async.cg.shared.global [%0], [%1], 16;" :: "r"(dst), "l"(src));
}
#define CP_COMMIT() asm volatile("cp.async.commit_group;")
#define CP_WAIT(N)  asm volatile("cp.async.wait_group %0;" :: "n"(N))

__global__ __launch_bounds__(NTHREADS, 2)
void fattn_mma(const float* __restrict__ qg, const float* __restrict__ kg,
               const float* __restrict__ vg, float* __restrict__ outg)
{
    extern __shared__ char smem[];
    const uint32_t smb = smem_u32(smem);
    const uint32_t sKb = smb + SK_OFF;
    const uint32_t sPb = smb + SP_OFF;
    const uint32_t sVb = smb + SV_OFF;

    const int tid  = threadIdx.x;
    const int lane = tid & 31;
    const int w    = tid >> 5;          // warp 0..3, owns q-rows 16w..16w+15
    const int g    = lane >> 2;
    const int tig  = lane & 3;
    const int mi   = lane >> 3;
    const int r8   = lane & 7;
    const int hiA  = mi >> 1;           // A-frag chunk offset (0/1)
    const int hiB  = lane >> 3;         // B-frag chunk offset (0..3)
    const int rowA = w*16 + (mi & 1)*8 + r8;

    const int qt = (int)(gridDim.x - 1 - blockIdx.x);   // heavy tiles first
    const int h  = blockIdx.y;
    const int b  = blockIdx.z;
    const int hk = h >> 2;
    const int q0 = qt * BQ;

    // ---- build Q A-fragments in registers (staged via sK as scratch) ----
    uint32_t qf[16][4];
    {
        const float qsc = 0.08838834764831845f * 1.4426950408889634f;
        const float* qs = qg + (size_t)(b*SEQ + q0)*QSTR + h*HD;
        #pragma unroll
        for (int i = 0; i < 16; i++) {
            int idx = i*NTHREADS + tid;
            int r = idx >> 5, c = idx & 31;
            float4 v = *(const float4*)(qs + (size_t)r*QSTR + c*4);
            v.x = tf32r(v.x*qsc); v.y = tf32r(v.y*qsc);
            v.z = tf32r(v.z*qsc); v.w = tf32r(v.w*qsc);
            *(float4*)(smem + SK_OFF + r*512 + ((c ^ (r & 7)) << 4)) = v;
        }
        __syncthreads();
        const uint32_t aQ = sKb + rowA*512;
        #pragma unroll
        for (int ks = 0; ks < 16; ks++)
            ldm4(qf[ks], aQ + (((2*ks + hiA) ^ r8) << 4));
        __syncthreads();   // sK scratch free for K0
    }

    const float* kbase = kg + (size_t)(b*SEQ)*KSTR + hk*HD;
    const float* vbase = vg + (size_t)(b*SEQ)*KSTR + hk*HD;

    // staging addresses for this thread (16 chunks each for K and V)
    const int sr = tid >> 3;            // not used; keep simple per-chunk math

    // ---- prologue: stage K0, V0 via cp.async ----
    {
        #pragma unroll
        for (int i = 0; i < 16; i++) {
            int idx = i*NTHREADS + tid;
            int r = idx >> 5, c = idx & 31;
            cpa16(sKb + r*512 + ((c ^ (r & 7)) << 4), kbase + (size_t)r*KSTR + c*4);
        }
        CP_COMMIT();
        #pragma unroll
        for (int i = 0; i < 16; i++) {
            int idx = i*NTHREADS + tid;
            int r = idx >> 5, c = idx & 31;
            cpa16(sVb + r*544 + c*16, vbase + (size_t)r*KSTR + c*4);
        }
        CP_COMMIT();
    }

    float o[16][4];
    #pragma unroll
    for (int nt = 0; nt < 16; nt++)
        o[nt][0] = o[nt][1] = o[nt][2] = o[nt][3] = 0.f;
    float l0 = 0.f, l8 = 0.f;

    const uint32_t aPbase = sPb + rowA*256;
    const uint32_t bKbase = sKb + r8*512;

    for (int kt = 0; kt <= qt; kt++) {
        // K(kt) arrived (V(kt) may still be in flight)
        CP_WAIT(1);
        __syncthreads();

        // ---- QK^T: S(16x64 per warp) = Q_w @ K^T ----
        float s[8][4];
        #pragma unroll
        for (int nt = 0; nt < 8; nt++)
            s[nt][0] = s[nt][1] = s[nt][2] = s[nt][3] = 0.f;
        #pragma unroll
        for (int kp = 0; kp < 8; kp++) {
            #pragma unroll
            for (int nt = 0; nt < 8; nt++) {
                uint32_t B[4];
                ldm4(B, bKbase + nt*4096 + (((4*kp + hiB) ^ r8) << 4));
                mma8(s[nt], qf[2*kp],     B[0], B[1]);
                mma8(s[nt], qf[2*kp + 1], B[2], B[3]);
            }
        }
        __syncthreads();   // all warps done reading sK

        // prefetch K(kt+1) into sK
        if (kt < qt) {
            const float* ksrc = kbase + (size_t)(kt + 1)*BK*KSTR;
            #pragma unroll
            for (int i = 0; i < 16; i++) {
                int idx = i*NTHREADS + tid;
                int r = idx >> 5, c = idx & 31;
                cpa16(sKb + r*512 + ((c ^ (r & 7)) << 4), ksrc + (size_t)r*KSTR + c*4);
            }
            CP_COMMIT();
        }

        // ---- softmax (max-free), rna P -> own-warp smem rows ----
        const bool diag = (kt == qt);
        const int rl0 = w*16 + g;
        #pragma unroll
        for (int nt = 0; nt < 8; nt++) {
            float p0 = exp2f(s[nt][0]);
            float p1 = exp2f(s[nt][1]);
            float p2 = exp2f(s[nt][2]);
            float p3 = exp2f(s[nt][3]);
            if (diag) {
                int c = nt*8 + 2*tig;
                if (c     > rl0)     p0 = 0.f;
                if (c + 1 > rl0)     p1 = 0.f;
                if (c     > rl0 + 8) p2 = 0.f;
                if (c + 1 > rl0 + 8) p3 = 0.f;
            }
            l0 += p0 + p1;
            l8 += p2 + p3;
            int swz = (((2*nt + (tig >> 1)) ^ g) << 4) + (tig & 1)*8;
            *(float2*)(smem + SP_OFF + rl0*256     + swz) =
                make_float2(tf32r(p0), tf32r(p1));
            *(float2*)(smem + SP_OFF + (rl0+8)*256 + swz) =
                make_float2(tf32r(p2), tf32r(p3));
        }
        __syncwarp();      // own P rows visible to own ldmatrix

        // V(kt) arrived (K(kt+1) may still be in flight)
        if (kt < qt) { CP_WAIT(1); } else { CP_WAIT(0); }
        __syncthreads();

        // ---- P·V: O += P_w(16x64) @ V(64x128) ----
        #pragma unroll
        for (int kp = 0; kp < 4; kp++) {
            uint32_t A0[4], A1[4];
            ldm4(A0, aPbase + (((4*kp     + hiA) ^ r8) << 4));
            ldm4(A1, aPbase + (((4*kp + 2 + hiA) ^ r8) << 4));
            #pragma unroll
            for (int nt = 0; nt < 16; nt++) {
                const char* vb = smem + SV_OFF + (8*nt + g)*4;
                uint32_t b00 = *(const uint32_t*)(vb + (16*kp + tig     )*544);
                uint32_t b01 = *(const uint32_t*)(vb + (16*kp + tig + 4 )*544);
                uint32_t b10 = *(const uint32_t*)(vb + (16*kp + tig + 8 )*544);
                uint32_t b11 = *(const uint32_t*)(vb + (16*kp + tig + 12)*544);
                mma8(o[nt], A0, b00, b01);
                mma8(o[nt], A1, b10, b11);
            }
        }
        __syncthreads();   // all warps done reading sV

        // prefetch V(kt+1) into sV
        if (kt < qt) {
            const float* vsrc = vbase + (size_t)(kt + 1)*BK*KSTR;
            #pragma unroll
            for (int i = 0; i < 16; i++) {
                int idx = i*NTHREADS + tid;
                int r = idx >> 5, c = idx & 31;
                cpa16(sVb + r*544 + c*16, vsrc + (size_t)r*KSTR + c*4);
            }
            CP_COMMIT();
        }
    }

    // ---- epilogue: quad-reduce l, normalize, store ----
    l0 += __shfl_xor_sync(0xffffffffu, l0, 1);
    l0 += __shfl_xor_sync(0xffffffffu, l0, 2);
    l8 += __shfl_xor_sync(0xffffffffu, l8, 1);
    l8 += __shfl_xor_sync(0xffffffffu, l8, 2);
    const float i0 = 1.0f / l0;
    const float i8 = 1.0f / l8;

    float* og = outg + (size_t)(b*SEQ + q0 + w*16 + g)*QSTR + h*HD + 2*tig;
    #pragma unroll
    for (int nt = 0; nt < 16; nt++) {
        *(float2*)(og + nt*8)          = make_float2(o[nt][0]*i0, o[nt][1]*i0);
        *(float2*)(og + 8*QSTR + nt*8) = make_float2(o[nt][2]*i8, o[nt][3]*i8);
    }
}

extern "C" void kernel_launch(void* const* d_in, const int* in_sizes, int n_in,
                              void* d_out, int out_size) {
    const float* q = (const float*)d_in[0];
    const float* k = (const float*)d_in[1];
    const float* v = (const float*)d_in[2];
    float* out = (float*)d_out;

    cudaFuncSetAttribute(fattn_mma, cudaFuncAttributeMaxDynamicSharedMemorySize,
                         SMEM_BYTES);
    dim3 grid(SEQ / BQ, NH, 2);   // (32, 32, 2)
    fattn_mma<<<grid, NTHREADS, SMEM_BYTES>>>(q, k, v, out);
}

// round 7
// speedup vs baseline: 4.9914x; 1.0081x over previous
#include <cuda_runtime.h>
#include <cstdint>

// Causal GQA attention via warp-level mma.sync tf32 (plain sm_103 target).
// B=2, S=2048, H=32, HK=8 (rep 4), D=128. fp32 in/out.
// Max-free softmax; Q as register A-fragments; K/V via cp.async pipeline;
// P stays in registers: QK C-fragments re-fed as PV A-fragments with a
// column permutation absorbed into V's row addressing (sigma = [0,2,4,6,1,3,5,7]).

#define SEQ 2048
#define NH 32
#define NHK 8
#define HD 128
#define QSTR (NH*HD)    // 4096
#define KSTR (NHK*HD)   // 1024
#define BQ 64
#define BK 64
#define NTHREADS 128

// smem layout (bytes)
#define SK_OFF 0                      // 64 rows x 512B, swizzled 16B chunks
#define SV_OFF 32768                  // 64 rows x 560B (128f + pad), linear
#define SMEM_BYTES (SV_OFF + 64*560)  // 68608

static __device__ __forceinline__ uint32_t smem_u32(const void* p){
    uint32_t a;
    asm("{ .reg .u64 t; cvta.to.shared.u64 t, %1; cvt.u32.u64 %0, t; }" : "=r"(a) : "l"(p));
    return a;
}
static __device__ __forceinline__ float tf32r(float x){
    uint32_t u;
    asm("cvt.rna.tf32.f32 %0, %1;" : "=r"(u) : "f"(x));
    return __uint_as_float(u);
}
static __device__ __forceinline__ void ldm4(uint32_t* r, uint32_t addr){
    asm volatile("ldmatrix.sync.aligned.m8n8.x4.shared.b16 {%0,%1,%2,%3}, [%4];"
                 : "=r"(r[0]), "=r"(r[1]), "=r"(r[2]), "=r"(r[3]) : "r"(addr));
}
static __device__ __forceinline__ void mma8(float* d, const uint32_t* a,
                                            uint32_t b0, uint32_t b1){
    asm volatile(
        "mma.sync.aligned.m16n8k8.row.col.f32.tf32.tf32.f32 "
        "{%0,%1,%2,%3}, {%4,%5,%6,%7}, {%8,%9}, {%0,%1,%2,%3};"
        : "+f"(d[0]), "+f"(d[1]), "+f"(d[2]), "+f"(d[3])
        : "r"(a[0]), "r"(a[1]), "r"(a[2]), "r"(a[3]), "r"(b0), "r"(b1));
}
static __device__ __forceinline__ void cpa16(uint32_t dst, const void* src){
    asm volatile("cp.async.cg.shared.global [%0], [%1], 16;" :: "r"(dst), "l"(src));
}
#define CP_COMMIT() asm volatile("cp.async.commit_group;")
#define CP_WAIT(N)  asm volatile("cp.async.wait_group %0;" :: "n"(N))

__global__ __launch_bounds__(NTHREADS, 2)
void fattn_mma(const float* __restrict__ qg, const float* __restrict__ kg,
               const float* __restrict__ vg, float* __restrict__ outg)
{
    extern __shared__ char smem[];
    const uint32_t smb = smem_u32(smem);
    const uint32_t sKb = smb + SK_OFF;
    const uint32_t sVb = smb + SV_OFF;

    const int tid  = threadIdx.x;
    const int lane = tid & 31;
    const int w    = tid >> 5;          // warp 0..3, owns q-rows 16w..16w+15
    const int g    = lane >> 2;
    const int tig  = lane & 3;
    const int mi   = lane >> 3;
    const int r8   = lane & 7;
    const int hiA  = mi >> 1;           // A-frag chunk offset (0/1)
    const int hiB  = lane >> 3;         // B-frag chunk offset (0..3)
    const int rowA = w*16 + (mi & 1)*8 + r8;

    const int qt = (int)(gridDim.x - 1 - blockIdx.x);   // heavy tiles first
    const int h  = blockIdx.y;
    const int b  = blockIdx.z;
    const int hk = h >> 2;
    const int q0 = qt * BQ;

    // ---- build Q A-fragments in registers (staged via sK as scratch) ----
    uint32_t qf[16][4];
    {
        const float qsc = 0.08838834764831845f * 1.4426950408889634f;
        const float* qs = qg + (size_t)(b*SEQ + q0)*QSTR + h*HD;
        #pragma unroll
        for (int i = 0; i < 16; i++) {
            int idx = i*NTHREADS + tid;
            int r = idx >> 5, c = idx & 31;
            float4 v = *(const float4*)(qs + (size_t)r*QSTR + c*4);
            v.x = tf32r(v.x*qsc); v.y = tf32r(v.y*qsc);
            v.z = tf32r(v.z*qsc); v.w = tf32r(v.w*qsc);
            *(float4*)(smem + SK_OFF + r*512 + ((c ^ (r & 7)) << 4)) = v;
        }
        __syncthreads();
        const uint32_t aQ = sKb + rowA*512;
        #pragma unroll
        for (int ks = 0; ks < 16; ks++)
            ldm4(qf[ks], aQ + (((2*ks + hiA) ^ r8) << 4));
        __syncthreads();   // sK scratch free for K0
    }

    const float* kbase = kg + (size_t)(b*SEQ)*KSTR + hk*HD;
    const float* vbase = vg + (size_t)(b*SEQ)*KSTR + hk*HD;

    // ---- prologue: stage K0, V0 via cp.async ----
    {
        #pragma unroll
        for (int i = 0; i < 16; i++) {
            int idx = i*NTHREADS + tid;
            int r = idx >> 5, c = idx & 31;
            cpa16(sKb + r*512 + ((c ^ (r & 7)) << 4), kbase + (size_t)r*KSTR + c*4);
        }
        CP_COMMIT();
        #pragma unroll
        for (int i = 0; i < 16; i++) {
            int idx = i*NTHREADS + tid;
            int r = idx >> 5, c = idx & 31;
            cpa16(sVb + r*560 + c*16, vbase + (size_t)r*KSTR + c*4);
        }
        CP_COMMIT();
    }

    float o[16][4];
    #pragma unroll
    for (int nt = 0; nt < 16; nt++)
        o[nt][0] = o[nt][1] = o[nt][2] = o[nt][3] = 0.f;
    float l0 = 0.f, l8 = 0.f;

    const uint32_t bKbase = sKb + r8*512;

    for (int kt = 0; kt <= qt; kt++) {
        // K(kt) arrived (V(kt) may still be in flight)
        CP_WAIT(1);
        __syncthreads();

        // ---- QK^T: S(16x64 per warp) = Q_w @ K^T ----
        float s[8][4];
        #pragma unroll
        for (int j = 0; j < 8; j++)
            s[j][0] = s[j][1] = s[j][2] = s[j][3] = 0.f;
        #pragma unroll
        for (int kp = 0; kp < 8; kp++) {
            #pragma unroll
            for (int j = 0; j < 8; j++) {
                uint32_t B[4];
                ldm4(B, bKbase + j*4096 + (((4*kp + hiB) ^ r8) << 4));
                mma8(s[j], qf[2*kp],     B[0], B[1]);
                mma8(s[j], qf[2*kp + 1], B[2], B[3]);
            }
        }
        __syncthreads();   // all warps done reading sK

        // prefetch K(kt+1) into sK
        if (kt < qt) {
            const float* ksrc = kbase + (size_t)(kt + 1)*BK*KSTR;
            #pragma unroll
            for (int i = 0; i < 16; i++) {
                int idx = i*NTHREADS + tid;
                int r = idx >> 5, c = idx & 31;
                cpa16(sKb + r*512 + ((c ^ (r & 7)) << 4), ksrc + (size_t)r*KSTR + c*4);
            }
            CP_COMMIT();
        }

        // ---- softmax (max-free): p = rna(exp2(s)); keep P in registers,
        //      pre-permuted (d0,d2,d1,d3) for direct use as PV A-fragments ----
        const bool diag = (kt == qt);
        const int rl0 = w*16 + g;
        uint32_t pr[8][4];
        #pragma unroll
        for (int j = 0; j < 8; j++) {
            float p0 = exp2f(s[j][0]);   // row g,   key 8j+2tig
            float p1 = exp2f(s[j][1]);   // row g,   key 8j+2tig+1
            float p2 = exp2f(s[j][2]);   // row g+8, key 8j+2tig
            float p3 = exp2f(s[j][3]);   // row g+8, key 8j+2tig+1
            if (diag) {
                int c = j*8 + 2*tig;
                if (c     > rl0)     p0 = 0.f;
                if (c + 1 > rl0)     p1 = 0.f;
                if (c     > rl0 + 8) p2 = 0.f;
                if (c + 1 > rl0 + 8) p3 = 0.f;
            }
            float r0 = tf32r(p0), r1 = tf32r(p1), r2 = tf32r(p2), r3 = tf32r(p3);
            l0 += r0 + r1;
            l8 += r2 + r3;
            pr[j][0] = __float_as_uint(r0);   // a0: row g,   sees key 2tig
            pr[j][1] = __float_as_uint(r2);   // a1: row g+8, sees key 2tig
            pr[j][2] = __float_as_uint(r1);   // a2: row g,   sees key 2tig+1
            pr[j][3] = __float_as_uint(r3);   // a3: row g+8, sees key 2tig+1
        }

        // V(kt) arrived (K(kt+1) may still be in flight)
        if (kt < qt) { CP_WAIT(1); } else { CP_WAIT(0); }
        __syncthreads();

        // ---- P·V: O += P_w(16x64) @ V(64x128), sigma-permuted V rows ----
        #pragma unroll
        for (int j = 0; j < 8; j++) {
            const char* vrow = smem + SV_OFF + (8*j + 2*tig)*560 + g*4;
            #pragma unroll
            for (int nt = 0; nt < 16; nt++) {
                uint32_t b0 = *(const uint32_t*)(vrow + nt*32);         // key 8j+2tig
                uint32_t b1 = *(const uint32_t*)(vrow + 560 + nt*32);   // key 8j+2tig+1
                mma8(o[nt], pr[j], b0, b1);
            }
        }
        __syncthreads();   // all warps done reading sV

        // prefetch V(kt+1) into sV
        if (kt < qt) {
            const float* vsrc = vbase + (size_t)(kt + 1)*BK*KSTR;
            #pragma unroll
            for (int i = 0; i < 16; i++) {
                int idx = i*NTHREADS + tid;
                int r = idx >> 5, c = idx & 31;
                cpa16(sVb + r*560 + c*16, vsrc + (size_t)r*KSTR + c*4);
            }
            CP_COMMIT();
        }
    }

    // ---- epilogue: quad-reduce l, normalize, store ----
    l0 += __shfl_xor_sync(0xffffffffu, l0, 1);
    l0 += __shfl_xor_sync(0xffffffffu, l0, 2);
    l8 += __shfl_xor_sync(0xffffffffu, l8, 1);
    l8 += __shfl_xor_sync(0xffffffffu, l8, 2);
    const float i0 = 1.0f / l0;
    const float i8 = 1.0f / l8;

    float* og = outg + (size_t)(b*SEQ + q0 + w*16 + g)*QSTR + h*HD + 2*tig;
    #pragma unroll
    for (int nt = 0; nt < 16; nt++) {
        *(float2*)(og + nt*8)          = make_float2(o[nt][0]*i0, o[nt][1]*i0);
        *(float2*)(og + 8*QSTR + nt*8) = make_float2(o[nt][2]*i8, o[nt][3]*i8);
    }
}

extern "C" void kernel_launch(void* const* d_in, const int* in_sizes, int n_in,
                              void* d_out, int out_size) {
    const float* q = (const float*)d_in[0];
    const float* k = (const float*)d_in[1];
    const float* v = (const float*)d_in[2];
    float* out = (float*)d_out;

    cudaFuncSetAttribute(fattn_mma, cudaFuncAttributeMaxDynamicSharedMemorySize,
                         SMEM_BYTES);
    dim3 grid(SEQ / BQ, NH, 2);   // (32, 32, 2)
    fattn_mma<<<grid, NTHREADS, SMEM_BYTES>>>(q, k, v, out);
}